// round 14
// baseline (speedup 1.0000x reference)
#include <cuda_runtime.h>
#include <cuda_bf16.h>
#include <math.h>
#include <stdint.h>

#define SEQ 512

typedef unsigned int u32;
typedef unsigned long long u64;
typedef signed char s8;

// ---------------- device globals (no cudaMalloc allowed) ----------------
// quantized integer-valued weights (fp32 storage of ints), gW[k*768 + gate*256 + j]
__device__ float gW1x[256 * 768];
__device__ float gW1h[256 * 768];
__device__ float gW2i[256 * 768];
__device__ float gW2h[256 * 768];

// activations as int16 split into two s8 planes: a = (256*hi + lo) * s_a
// x: s_a = 2^-12 ; h: s_a = 2^-14
__device__ __align__(128) s8 g_xhi8[(size_t)SEQ * 65536];
__device__ __align__(128) s8 g_xlo8[(size_t)SEQ * 65536];
__device__ __align__(128) s8 g_h1hi8[2][65536];
__device__ __align__(128) s8 g_h1lo8[2][65536];
__device__ __align__(128) s8 g_h2hi8[2][65536];
__device__ __align__(128) s8 g_h2lo8[2][65536];

__device__ float g_scale[4];
__device__ unsigned g_ctr[8 * 32];

// ---------------- helpers ----------------
__device__ __forceinline__ u32 smem_u32(const void* p) {
    u32 a;
    asm("{ .reg .u64 t; cvta.to.shared.u64 t, %1; cvt.u32.u64 %0, t; }" : "=r"(a) : "l"(p));
    return a;
}

#define LDMATRIX4(r, a) \
    asm volatile("ldmatrix.sync.aligned.m8n8.x4.shared.b16 {%0,%1,%2,%3}, [%4];" \
        : "=r"((r)[0]), "=r"((r)[1]), "=r"((r)[2]), "=r"((r)[3]) : "r"(a))

#define IMMA(d, a, b0, b1) \
    asm volatile("mma.sync.aligned.m16n8k32.row.col.s32.s8.s8.s32 " \
        "{%0,%1,%2,%3}, {%4,%5,%6,%7}, {%8,%9}, {%0,%1,%2,%3};" \
        : "+r"((d)[0]), "+r"((d)[1]), "+r"((d)[2]), "+r"((d)[3]) \
        : "r"((a)[0]), "r"((a)[1]), "r"((a)[2]), "r"((a)[3]), "r"(b0), "r"(b1))

#define LDS128R(r0, r1, r2, r3, a) \
    asm volatile("ld.shared.v4.b32 {%0,%1,%2,%3}, [%4];" \
        : "=r"(r0), "=r"(r1), "=r"(r2), "=r"(r3) : "r"(a))

#define LDSU16(r0, a) \
    asm volatile("ld.shared.u16 %0, [%1];" : "=r"(r0) : "r"(a))

#define CPA16(dst, src) \
    asm volatile("cp.async.cg.shared.global [%0], [%1], 16;" :: "r"(dst), "l"(src) : "memory")
#define CPA_COMMIT() asm volatile("cp.async.commit_group;" ::: "memory")
#define CPA_WAIT(N)  asm volatile("cp.async.wait_group %0;" :: "n"(N) : "memory")

__device__ __forceinline__ float sigf(float x) { return 1.f / (1.f + expf(-x)); }

__device__ __forceinline__ void split16(float v, float sc, s8& hi, s8& lo) {
    int xi = (int)rintf(v * sc);
    xi = max(-32639, min(32639, xi));
    int h = (xi + 128) >> 8;
    hi = (s8)h;
    lo = (s8)(xi - (h << 8));
}

// ---------------- setup kernels ----------------
__global__ void k_init(const float* __restrict__ h1, const float* __restrict__ h2) {
    int i = blockIdx.x * blockDim.x + threadIdx.x;
    if (i < 256) g_ctr[i] = 0u;
    if (i < 65536) {
        s8 a, b;
        split16(h1[i], 16384.f, a, b);
        g_h1hi8[0][i] = a; g_h1lo8[0][i] = b;          // h1(0) -> slot 0
        split16(h2[i], 16384.f, a, b);
        g_h2hi8[0][i] = a; g_h2lo8[0][i] = b;          // h2(0) -> slot 0
    }
}

__global__ void k_scales(const float* __restrict__ w0, const float* __restrict__ w1,
                         const float* __restrict__ w2, const float* __restrict__ w3) {
    const float* w = (blockIdx.x == 0) ? w0 : (blockIdx.x == 1) ? w1
                   : (blockIdx.x == 2) ? w2 : w3;
    const int n = 768 * 256;
    float m = 0.f;
    for (int i = threadIdx.x; i < n; i += blockDim.x) m = fmaxf(m, fabsf(w[i]));
    __shared__ float sm[512];
    sm[threadIdx.x] = m;
    __syncthreads();
    for (int s = blockDim.x >> 1; s > 0; s >>= 1) {
        if (threadIdx.x < s) sm[threadIdx.x] = fmaxf(sm[threadIdx.x], sm[threadIdx.x + s]);
        __syncthreads();
    }
    if (threadIdx.x == 0) g_scale[blockIdx.x] = sm[0] / 127.0f;
}

// gW[k*768 + c] = rint(W[c*256 + k] / s)   (c = gate*256 + j; |v| <= 127)
__global__ void k_pack(const float* __restrict__ wih1, const float* __restrict__ whh1,
                       const float* __restrict__ wih2, const float* __restrict__ whh2) {
    const float s0 = g_scale[0], s1 = g_scale[1], s2 = g_scale[2], s3 = g_scale[3];
    const int N = 256 * 768;
    for (int i = blockIdx.x * blockDim.x + threadIdx.x; i < N;
         i += gridDim.x * blockDim.x) {
        int k = i / 768, c = i - k * 768;
        int off = c * 256 + k;
        gW1x[i] = rintf(wih1[off] / s0);
        gW1h[i] = rintf(whh1[off] / s1);
        gW2i[i] = rintf(wih2[off] / s2);
        gW2h[i] = rintf(whh2[off] / s3);
    }
}

// x -> int16 split planes, scale 2^12
__global__ void k_convx(const float* __restrict__ x) {
    size_t i = ((size_t)blockIdx.x * blockDim.x + threadIdx.x) * 4;
    if (i >= (size_t)SEQ * 65536) return;
    float4 v = *(const float4*)(x + i);
    float vv[4] = {v.x, v.y, v.z, v.w};
    s8 hi[4], lo[4];
    #pragma unroll
    for (int r = 0; r < 4; ++r) split16(vv[r], 4096.f, hi[r], lo[r]);
    *(u32*)(g_xhi8 + i) = *(u32*)hi;
    *(u32*)(g_xlo8 + i) = *(u32*)lo;
}

// ---------------- main persistent kernel ----------------
// 128 CTAs x 256 threads = 8 bt-groups x 16 jt. Per CTA: M=32 rows x N=48 (gate-major),
// warps 0-3 = L1 phase s (h1(s+1)), warps 4-7 = L2 phase s (h2(s)).
// A planes (s8, 256B/row, stride 272): [0]=x-hi [1]=x-lo [2]=h1-hi [3]=h1-lo [4]=h2-hi [5]=h2-lo
// B stream: [stream(4)][tile(6)][cp(4)][lane(32)][16B], stream = wg*2+src
#define S_BF   1024
#define S_A    50176
#define A_STR  272
#define A_PL   8704
#define SMEM_BYTES 102400

__global__ void __launch_bounds__(256) k_main(
    const float* __restrict__ b_ih1, const float* __restrict__ b_hh1,
    const float* __restrict__ b_ih2, const float* __restrict__ b_hh2,
    float* __restrict__ out)
{
    extern __shared__ char smem[];
    const u32 sbase = smem_u32(smem);
    float* sBias = (float*)smem;

    const int tid = threadIdx.x;
    const int ln = tid & 31, w = tid >> 5;
    const int wg = w >> 2;               // 0 = layer1, 1 = layer2
    const int wm = w & 1;                // 16-row half
    const int wn = (w >> 1) & 1;         // j-half of 8
    const int bid = blockIdx.x;
    const int bt = bid >> 4;
    const int jt = bid & 15;
    const int b0 = bt * 32;
    const int j0 = jt * 16;

    unsigned* ctr = &g_ctr[bt * 32];

    // ---- one-time: int8 B fragment stream
    // warp w: stream st = w&3, chunk-pairs cp in {(w>>2)*2, (w>>2)*2+1}
    {
        const int st = w & 3;
        const float* Ws = (st == 0) ? gW1x : (st == 1) ? gW1h : (st == 2) ? gW2i : gW2h;
        const int n = ln >> 2, kq = ln & 3;
        for (int cp = (w >> 2) * 2; cp < (w >> 2) * 2 + 2; ++cp) {
            #pragma unroll
            for (int tt = 0; tt < 6; ++tt) {
                int j = j0 + (tt & 1) * 8 + n;
                int c = (tt >> 1) * 256 + j;
                u32 words[4];
                #pragma unroll
                for (int cc = 0; cc < 2; ++cc) {
                    int k0 = (cp * 2 + cc) * 32;
                    u32 w0 = 0, w1 = 0;
                    #pragma unroll
                    for (int e = 0; e < 4; ++e) {
                        int v0 = (int)rintf(Ws[(size_t)(k0 + kq * 4 + e) * 768 + c]);
                        int v1 = (int)rintf(Ws[(size_t)(k0 + 16 + kq * 4 + e) * 768 + c]);
                        w0 |= ((u32)(unsigned char)(s8)v0) << (e * 8);
                        w1 |= ((u32)(unsigned char)(s8)v1) << (e * 8);
                    }
                    words[cc * 2 + 0] = w0;
                    words[cc * 2 + 1] = w1;
                }
                u32 ad = sbase + S_BF + (u32)((((st * 6 + tt) * 4 + cp) * 32 + ln) * 16);
                asm volatile("st.shared.v4.b32 [%0], {%1,%2,%3,%4};"
                    :: "r"(ad), "r"(words[0]), "r"(words[1]), "r"(words[2]), "r"(words[3])
                    : "memory");
            }
        }
    }
    if (tid < 32) {
        int lj = tid & 15;
        int j = j0 + lj;
        const float* bi = (tid < 16) ? b_ih1 : b_ih2;
        const float* bh = (tid < 16) ? b_hh1 : b_hh2;
        sBias[tid * 4 + 0] = bi[j] + bh[j];
        sBias[tid * 4 + 1] = bi[j + 256] + bh[j + 256];
        sBias[tid * 4 + 2] = bi[j + 512];
        sBias[tid * 4 + 3] = bh[j + 512];
    }
    // epilogue combine constants: gate = C * (float)(256*accH + accL)
    const float Ci = (wg == 0) ? g_scale[0] * (1.f / 4096.f)  : g_scale[2] * (1.f / 16384.f);
    const float Ch = (wg == 0) ? g_scale[1] * (1.f / 16384.f) : g_scale[3] * (1.f / 16384.f);
    __syncthreads();

    // per-lane constants
    const int jb = j0 + wn * 8 + (ln & 3) * 2;      // global j of col pair
    const int b_r = b0 + wm * 16 + (ln >> 2);       // global batch row
    const int jl = wg * 16 + wn * 8 + (ln & 3) * 2;
    float bR[2], bZ[2], bNi[2], bNh[2];
    #pragma unroll
    for (int cc = 0; cc < 2; ++cc) {
        bR[cc]  = sBias[(jl + cc) * 4 + 0];
        bZ[cc]  = sBias[(jl + cc) * 4 + 1];
        bNi[cc] = sBias[(jl + cc) * 4 + 2];
        bNh[cc] = sBias[(jl + cc) * 4 + 3];
    }
    const u32 lane_off = (u32)(wm * 16 + (ln & 15)) * A_STR + (u32)((ln >> 4) * 16);
    const u32 h_base = sbase + S_A + (u32)(2 + wg * 2) * A_PL
                     + (u32)(wm * 16 + (ln >> 2)) * A_STR + (u32)jb;
    // staging map: st_pr = plane-row (2 planes x 32 rows), 4 x 64B segments
    const int st_q   = (tid >> 2) >> 5;
    const int st_row = (tid >> 2) & 31;
    const int st_seg = (tid & 3) * 64;

    #define STAGE(PHI, PLO, PB) do { \
        const char* _s = (const char*)(st_q ? (const void*)(PLO) : (const void*)(PHI)) \
                       + (size_t)(b0 + st_row) * 256 + st_seg; \
        u32 _d = sbase + S_A + (u32)((PB) + st_q) * A_PL + (u32)st_row * A_STR + (u32)st_seg; \
        CPA16(_d, _s); CPA16(_d + 16, _s + 16); \
        CPA16(_d + 32, _s + 32); CPA16(_d + 48, _s + 48); \
        CPA_COMMIT(); \
    } while (0)

    for (int sph = 0; sph <= SEQ; ++sph) {
        const bool act1 = (sph < SEQ);
        const bool act2 = (sph >= 1);
        const bool myact = wg ? act2 : act1;

        // G0: x(sph) (before the wait; no cross-phase dependency)
        if (act1) {
            STAGE(g_xhi8 + (size_t)sph * 65536, g_xlo8 + (size_t)sph * 65536, 0);
        } else { CPA_COMMIT(); }

        // group-local wait: all 16 CTAs finished phase sph-1
        if (sph > 0) {
            if (tid == 0) {
                unsigned tgt = 16u * (unsigned)sph;
                while (*(volatile unsigned*)ctr < tgt) { }
                __threadfence();
            }
            __syncthreads();
        }

        // G1: h1(sph) slot sph&1 ; G2: h2(sph-1) slot (sph-1)&1
        {
            const int s1 = sph & 1, s2 = (sph - 1) & 1;
            STAGE(g_h1hi8[s1], g_h1lo8[s1], 2);
            STAGE(g_h2hi8[s2], g_h2lo8[s2], 4);
        }

        int aiH[3][4] = {}, aiL[3][4] = {}, ahH[3][4] = {}, ahL[3][4] = {};

        // src-half 0 (i-src): wg0 -> x (G0), wg1 -> h1 (G1)
        // src-half 1 (h-src): wg0 -> h1 (G1), wg1 -> h2 (G2)
        #pragma unroll
        for (int s01 = 0; s01 < 2; ++s01) {
            if (s01 == 0) { CPA_WAIT(1); } else { CPA_WAIT(0); }
            __syncthreads();
            if (myact) {
                const u32 Ab = sbase + S_A + (u32)((wg + s01) * 2) * A_PL + lane_off;
                const u32 Bb = sbase + S_BF + (u32)((wg * 2 + s01) * 6 * 4 * 32 * 16);
                #pragma unroll
                for (int cp = 0; cp < 4; ++cp) {
                    u32 ah0[4], al0[4], ah1[4], al1[4];
                    LDMATRIX4(ah0, Ab + (u32)(cp * 64));
                    LDMATRIX4(ah1, Ab + (u32)(cp * 64 + 32));
                    LDMATRIX4(al0, Ab + A_PL + (u32)(cp * 64));
                    LDMATRIX4(al1, Ab + A_PL + (u32)(cp * 64 + 32));
                    #pragma unroll
                    for (int g = 0; g < 3; ++g) {
                        u32 f0, f1, f2, f3;
                        u32 bad = Bb + (u32)(((((g * 2 + wn) * 4) + cp) * 32 + ln) * 16);
                        LDS128R(f0, f1, f2, f3, bad);
                        int* dH = s01 ? ahH[g] : aiH[g];
                        int* dL = s01 ? ahL[g] : aiL[g];
                        IMMA(dH, ah0, f0, f1);
                        IMMA(dL, al0, f0, f1);
                        IMMA(dH, ah1, f2, f3);
                        IMMA(dL, al1, f2, f3);
                    }
                }
            }
        }

        // ---- epilogue: gates in registers; h_old from staged planes (int16 exact)
        if (myact) {
            float res[2][2];
            #pragma unroll
            for (int rh = 0; rh < 2; ++rh) {
                u32 hw, lw;
                LDSU16(hw, h_base + (u32)(rh * 8) * A_STR);
                LDSU16(lw, h_base + (u32)(rh * 8) * A_STR + A_PL);
                float hold[2];
                #pragma unroll
                for (int cc = 0; cc < 2; ++cc) {
                    int hb = (int)(s8)((hw >> (cc * 8)) & 255);
                    int lb = (int)(s8)((lw >> (cc * 8)) & 255);
                    hold[cc] = (float)(hb * 256 + lb) * (1.f / 16384.f);
                }
                #pragma unroll
                for (int cc = 0; cc < 2; ++cc) {
                    const int k = rh * 2 + cc;
                    float giR = Ci * (float)(aiH[0][k] * 256 + aiL[0][k]);
                    float giZ = Ci * (float)(aiH[1][k] * 256 + aiL[1][k]);
                    float giN = Ci * (float)(aiH[2][k] * 256 + aiL[2][k]);
                    float ghR = Ch * (float)(ahH[0][k] * 256 + ahL[0][k]);
                    float ghZ = Ch * (float)(ahH[1][k] * 256 + ahL[1][k]);
                    float ghN = Ch * (float)(ahH[2][k] * 256 + ahL[2][k]);
                    float r = sigf(giR + ghR + bR[cc]);
                    float z = sigf(giZ + ghZ + bZ[cc]);
                    float n = tanhf(giN + bNi[cc] + r * (ghN + bNh[cc]));
                    res[rh][cc] = (1.f - z) * n + z * hold[cc];
                }
            }
            if (wg == 1 && sph == SEQ) {
                *(float2*)(out + (size_t)b_r * 256 + jb) = make_float2(res[0][0], res[0][1]);
                *(float2*)(out + (size_t)(b_r + 8) * 256 + jb) = make_float2(res[1][0], res[1][1]);
            } else {
                s8* hhi; s8* hlo;
                if (wg == 0) { const int ws = (sph + 1) & 1; hhi = g_h1hi8[ws]; hlo = g_h1lo8[ws]; }
                else         { const int ws = sph & 1;       hhi = g_h2hi8[ws]; hlo = g_h2lo8[ws]; }
                #pragma unroll
                for (int rh = 0; rh < 2; ++rh) {
                    const size_t off = (size_t)(b_r + rh * 8) * 256 + jb;
                    s8 h0, l0, h1b, l1b;
                    split16(res[rh][0], 16384.f, h0, l0);
                    split16(res[rh][1], 16384.f, h1b, l1b);
                    unsigned short hp = (unsigned short)((unsigned char)h0
                                        | ((unsigned)(unsigned char)h1b << 8));
                    unsigned short lp = (unsigned short)((unsigned char)l0
                                        | ((unsigned)(unsigned char)l1b << 8));
                    *(unsigned short*)(hhi + off) = hp;
                    *(unsigned short*)(hlo + off) = lp;
                }
            }
        }

        // ---- arrive
        __syncthreads();
        if (tid == 0) {
            __threadfence();
            atomicAdd(ctr, 1u);
        }
    }
    #undef STAGE
}

// ---------------- host launch ----------------
extern "C" void kernel_launch(void* const* d_in, const int* in_sizes, int n_in,
                              void* d_out, int out_size) {
    (void)in_sizes; (void)n_in; (void)out_size;
    const float* x     = (const float*)d_in[0];
    const float* h1    = (const float*)d_in[1];
    const float* h2    = (const float*)d_in[2];
    const float* w_ih1 = (const float*)d_in[3];
    const float* w_hh1 = (const float*)d_in[4];
    const float* b_ih1 = (const float*)d_in[5];
    const float* b_hh1 = (const float*)d_in[6];
    const float* w_ih2 = (const float*)d_in[7];
    const float* w_hh2 = (const float*)d_in[8];
    const float* b_ih2 = (const float*)d_in[9];
    const float* b_hh2 = (const float*)d_in[10];
    float* out = (float*)d_out;

    cudaFuncSetAttribute(k_main, cudaFuncAttributeMaxDynamicSharedMemorySize, SMEM_BYTES);

    k_init<<<256, 256>>>(h1, h2);
    k_scales<<<4, 512>>>(w_ih1, w_hh1, w_ih2, w_hh2);
    k_pack<<<512, 256>>>(w_ih1, w_hh1, w_ih2, w_hh2);
    k_convx<<<32768, 256>>>(x);
    k_main<<<128, 256, SMEM_BYTES>>>(b_ih1, b_hh1, b_ih2, b_hh2, out);
}

// round 15
// speedup vs baseline: 1.2818x; 1.2818x over previous
#include <cuda_runtime.h>
#include <cuda_bf16.h>
#include <math.h>
#include <stdint.h>

#define SEQ 512

typedef unsigned int u32;
typedef unsigned long long u64;

// ---------------- device globals (no cudaMalloc allowed) ----------------
// quantized integer-valued weights (bf16-exact), layout gW[k*768 + c], c = gate*256 + j
__device__ float gW1x[256 * 768];
__device__ float gW1h[256 * 768];
__device__ float gW2i[256 * 768];
__device__ float gW2h[256 * 768];

// activations as bf16 hi/lo planes, [b][k] row-major
__device__ __nv_bfloat16 g_xhi[(size_t)SEQ * 65536];
__device__ __nv_bfloat16 g_xlo[(size_t)SEQ * 65536];
// h(m) stored in slot m&1
__device__ __nv_bfloat16 g_h1hi[2][65536];
__device__ __nv_bfloat16 g_h1lo[2][65536];
__device__ __nv_bfloat16 g_h2hi[2][65536];
__device__ __nv_bfloat16 g_h2lo[2][65536];

__device__ float g_scale[4];
// per-bt-group progress counters (one cache line each)
__device__ unsigned g_ctr[8 * 32];

// ---------------- helpers ----------------
__device__ __forceinline__ u32 smem_u32(const void* p) {
    u32 a;
    asm("{ .reg .u64 t; cvta.to.shared.u64 t, %1; cvt.u32.u64 %0, t; }" : "=r"(a) : "l"(p));
    return a;
}

#define LDMATRIX4(r, a) \
    asm volatile("ldmatrix.sync.aligned.m8n8.x4.shared.b16 {%0,%1,%2,%3}, [%4];" \
        : "=r"((r)[0]), "=r"((r)[1]), "=r"((r)[2]), "=r"((r)[3]) : "r"(a))

#define MMA16816(d, a, b0, b1) \
    asm volatile("mma.sync.aligned.m16n8k16.row.col.f32.bf16.bf16.f32 " \
        "{%0,%1,%2,%3}, {%4,%5,%6,%7}, {%8,%9}, {%0,%1,%2,%3};" \
        : "+f"((d)[0]), "+f"((d)[1]), "+f"((d)[2]), "+f"((d)[3]) \
        : "r"((a)[0]), "r"((a)[1]), "r"((a)[2]), "r"((a)[3]), "r"(b0), "r"(b1))

#define LDS128R(r0, r1, r2, r3, a) \
    asm volatile("ld.shared.v4.b32 {%0,%1,%2,%3}, [%4];" \
        : "=r"(r0), "=r"(r1), "=r"(r2), "=r"(r3) : "r"(a))

#define LDS32(r0, a) \
    asm volatile("ld.shared.b32 %0, [%1];" : "=r"(r0) : "r"(a))

#define CPA16(dst, src) \
    asm volatile("cp.async.cg.shared.global [%0], [%1], 16;" :: "r"(dst), "l"(src) : "memory")
#define CPA_COMMIT() asm volatile("cp.async.commit_group;" ::: "memory")
#define CPA_WAIT(N)  asm volatile("cp.async.wait_group %0;" :: "n"(N) : "memory")

__device__ __forceinline__ u32 pkbf(float x, float y) {
    __nv_bfloat162 t = __floats2bfloat162_rn(x, y);
    return *(u32*)&t;
}

__device__ __forceinline__ float sigf(float x) { return 1.f / (1.f + expf(-x)); }

// ---------------- setup kernels ----------------
__global__ void k_init(const float* __restrict__ h1, const float* __restrict__ h2) {
    int i = blockIdx.x * blockDim.x + threadIdx.x;
    if (i < 256) g_ctr[i] = 0u;
    if (i < 65536) {
        float v1 = h1[i], v2 = h2[i];
        __nv_bfloat16 a = __float2bfloat16(v1);
        g_h1hi[0][i] = a;                                  // h1(0) -> slot 0
        g_h1lo[0][i] = __float2bfloat16(v1 - __bfloat162float(a));
        __nv_bfloat16 b = __float2bfloat16(v2);
        g_h2hi[0][i] = b;                                  // h2(0) -> slot 0
        g_h2lo[0][i] = __float2bfloat16(v2 - __bfloat162float(b));
    }
}

__global__ void k_scales(const float* __restrict__ w0, const float* __restrict__ w1,
                         const float* __restrict__ w2, const float* __restrict__ w3) {
    const float* w = (blockIdx.x == 0) ? w0 : (blockIdx.x == 1) ? w1
                   : (blockIdx.x == 2) ? w2 : w3;
    const int n = 768 * 256;
    float m = 0.f;
    for (int i = threadIdx.x; i < n; i += blockDim.x) m = fmaxf(m, fabsf(w[i]));
    __shared__ float sm[512];
    sm[threadIdx.x] = m;
    __syncthreads();
    for (int s = blockDim.x >> 1; s > 0; s >>= 1) {
        if (threadIdx.x < s) sm[threadIdx.x] = fmaxf(sm[threadIdx.x], sm[threadIdx.x + s]);
        __syncthreads();
    }
    if (threadIdx.x == 0) g_scale[blockIdx.x] = sm[0] / 127.0f;
}

// gW[k*768 + c] = rint(W[c*256 + k] / s)   (c = gate*256 + j; |v| <= 127, bf16-exact)
__global__ void k_pack(const float* __restrict__ wih1, const float* __restrict__ whh1,
                       const float* __restrict__ wih2, const float* __restrict__ whh2) {
    const float s0 = g_scale[0], s1 = g_scale[1], s2 = g_scale[2], s3 = g_scale[3];
    const int N = 256 * 768;
    for (int i = blockIdx.x * blockDim.x + threadIdx.x; i < N;
         i += gridDim.x * blockDim.x) {
        int k = i / 768, c = i - k * 768;
        int off = c * 256 + k;
        gW1x[i] = rintf(wih1[off] / s0);
        gW1h[i] = rintf(whh1[off] / s1);
        gW2i[i] = rintf(wih2[off] / s2);
        gW2h[i] = rintf(whh2[off] / s3);
    }
}

// x -> bf16 hi/lo planes
__global__ void k_convx(const float* __restrict__ x) {
    size_t i = ((size_t)blockIdx.x * blockDim.x + threadIdx.x) * 4;
    if (i >= (size_t)SEQ * 65536) return;
    float4 v = *(const float4*)(x + i);
    float vv[4] = {v.x, v.y, v.z, v.w};
    __nv_bfloat16 hi[4], lo[4];
    #pragma unroll
    for (int r = 0; r < 4; ++r) {
        hi[r] = __float2bfloat16(vv[r]);
        lo[r] = __float2bfloat16(vv[r] - __bfloat162float(hi[r]));
    }
    *(uint2*)(g_xhi + i) = *(uint2*)hi;
    *(uint2*)(g_xlo + i) = *(uint2*)lo;
}

// ---------------- main persistent kernel ----------------
// 128 CTAs x 256 threads = 8 bt-groups x 16 jt. Per CTA: M=32 rows x N=48 (gate-major),
// warps 0-3 = L1 phase s (h1(s+1)), warps 4-7 = L2 phase s (h2(s)).
// L1's x-GEMM runs BEFORE the group counter wait (x has no cross-phase dependency);
// only the h-GEMMs sit on the post-wait critical path.
// A planes (bf16, stride 528): [0]=x-hi [1]=x-lo [2]=h1-hi [3]=h1-lo [4]=h2-hi [5]=h2-lo.
// B frag stream: [stream(4)][tile(6)][kpg(8)][lane(32)][16B], stream = wg*2+src.
#define S_BF   1024
#define S_A    99328
#define A_STR  528
#define A_PL   16896
#define B_STRM 24576
#define SMEM_BYTES 200704

__global__ void __launch_bounds__(256) k_main(
    const float* __restrict__ b_ih1, const float* __restrict__ b_hh1,
    const float* __restrict__ b_ih2, const float* __restrict__ b_hh2,
    float* __restrict__ out)
{
    extern __shared__ char smem[];
    const u32 sbase = smem_u32(smem);
    float* sBias = (float*)smem;

    const int tid = threadIdx.x;
    const int ln = tid & 31, w = tid >> 5;
    const int wg = w >> 2;               // 0 = layer1, 1 = layer2
    const int wm = w & 1;                // 16-row half
    const int wn = (w >> 1) & 1;         // j-half of 8
    const int bid = blockIdx.x;
    const int bt = bid >> 4;
    const int jt = bid & 15;
    const int b0 = bt * 32;
    const int j0 = jt * 16;

    unsigned* ctr = &g_ctr[bt * 32];

    // ---- one-time: B fragment stream (both layers; paired 16B per 2 ksteps)
    {
        const int sB = w & 1;
        const int ksh = (w >> 1) & 1;
        const float* Ws;
        if (wg == 0) Ws = sB ? gW1h : gW1x;
        else         Ws = sB ? gW2h : gW2i;
        const int n = ln >> 2, kp4 = ln & 3;
        for (int ks = ksh * 8; ks < ksh * 8 + 8; ++ks) {
            #pragma unroll
            for (int tt = 0; tt < 6; ++tt) {
                int j = j0 + (tt & 1) * 8 + n;
                int c = (tt >> 1) * 256 + j;
                int k0 = ks * 16 + kp4 * 2;
                u32 f0 = pkbf(Ws[(size_t)k0 * 768 + c], Ws[(size_t)(k0 + 1) * 768 + c]);
                u32 f1 = pkbf(Ws[(size_t)(k0 + 8) * 768 + c], Ws[(size_t)(k0 + 9) * 768 + c]);
                u32 ad = sbase + S_BF
                       + (u32)(((((wg * 2 + sB) * 6 + tt) * 8 + (ks >> 1)) * 32 + ln) * 16)
                       + (u32)((ks & 1) * 8);
                asm volatile("st.shared.v2.b32 [%0], {%1,%2};" :: "r"(ad), "r"(f0), "r"(f1) : "memory");
            }
        }
    }
    if (tid < 32) {
        int lj = tid & 15;
        int j = j0 + lj;
        const float* bi = (tid < 16) ? b_ih1 : b_ih2;
        const float* bh = (tid < 16) ? b_hh1 : b_hh2;
        sBias[tid * 4 + 0] = bi[j] + bh[j];
        sBias[tid * 4 + 1] = bi[j + 256] + bh[j + 256];
        sBias[tid * 4 + 2] = bi[j + 512];
        sBias[tid * 4 + 3] = bh[j + 512];
    }
    const float s_i = (wg == 0) ? g_scale[0] : g_scale[2];
    const float s_h = (wg == 0) ? g_scale[1] : g_scale[3];
    __syncthreads();

    // per-lane constants
    const int jb = j0 + wn * 8 + (ln & 3) * 2;      // global j of col pair
    const int b_r = b0 + wm * 16 + (ln >> 2);       // global batch row
    const int jl = wg * 16 + wn * 8 + (ln & 3) * 2;
    float bR[2], bZ[2], bNi[2], bNh[2];
    #pragma unroll
    for (int cc = 0; cc < 2; ++cc) {
        bR[cc]  = sBias[(jl + cc) * 4 + 0];
        bZ[cc]  = sBias[(jl + cc) * 4 + 1];
        bNi[cc] = sBias[(jl + cc) * 4 + 2];
        bNh[cc] = sBias[(jl + cc) * 4 + 3];
    }
    const u32 a_base = sbase + S_A + (u32)(wm * 16 + (ln & 15)) * A_STR + (u32)((ln >> 4) * 16);
    // h_old planes: L1 -> h1 (planes 2,3); L2 -> h2 (planes 4,5)
    const u32 h_base = sbase + S_A + (u32)(2 + wg * 2) * A_PL
                     + (u32)(wm * 16 + (ln >> 2)) * A_STR + (u32)(jb * 2);
    // staging map: 4 threads per plane-row
    const int st_q   = (tid >> 2) >> 5;        // plane within pair
    const int st_row = (tid >> 2) & 31;
    const int st_seg = (tid & 3) * 64;

    #define STAGE(PHI, PLO, PB, KH) do { \
        const char* _s = (const char*)(st_q ? (const void*)(PLO) : (const void*)(PHI)) \
                       + (size_t)(b0 + st_row) * 512 + (KH) * 256 + st_seg; \
        u32 _d = sbase + S_A + (u32)((PB) + st_q) * A_PL + (u32)st_row * A_STR \
               + (u32)((KH) * 256 + st_seg); \
        CPA16(_d, _s); CPA16(_d + 16, _s + 16); \
        CPA16(_d + 32, _s + 32); CPA16(_d + 48, _s + 48); \
    } while (0)

    // one kpg step (2 ksteps of 16) of one source into ACC[3][4]
    #define KSTEP(APL0, BB, ACC, KPG) do { \
        u32 aE0[4], aE1[4], aO0[4], aO1[4]; \
        LDMATRIX4(aE0, (APL0) + (u32)((KPG) * 64)); \
        LDMATRIX4(aO0, (APL0) + (u32)((KPG) * 64 + 32)); \
        LDMATRIX4(aE1, (APL0) + A_PL + (u32)((KPG) * 64)); \
        LDMATRIX4(aO1, (APL0) + A_PL + (u32)((KPG) * 64 + 32)); \
        _Pragma("unroll") \
        for (int g = 0; g < 3; ++g) { \
            u32 f0, f1, f2, f3; \
            u32 bad = (BB) + (u32)((((g * 2 + wn) * 8 + (KPG)) * 32 + ln) * 16); \
            LDS128R(f0, f1, f2, f3, bad); \
            MMA16816(ACC[g], aE0, f0, f1); \
            MMA16816(ACC[g], aE1, f0, f1); \
            MMA16816(ACC[g], aO0, f2, f3); \
            MMA16816(ACC[g], aO1, f2, f3); \
        } \
    } while (0)

    for (int sph = 0; sph <= SEQ; ++sph) {
        const bool act1 = (sph < SEQ);
        const bool act2 = (sph >= 1);
        const bool myact = wg ? act2 : act1;

        // ---- stage x(sph) (no cross-phase dependency)
        if (act1) {
            const __nv_bfloat16* xh = g_xhi + (size_t)sph * 65536;
            const __nv_bfloat16* xl = g_xlo + (size_t)sph * 65536;
            STAGE(xh, xl, 0, 0); CPA_COMMIT();
            STAGE(xh, xl, 0, 1); CPA_COMMIT();
        } else { CPA_COMMIT(); CPA_COMMIT(); }
        CPA_WAIT(0);
        __syncthreads();

        float acci[3][4] = {}, acch[3][4] = {};

        // ---- pre-wait: L1 x-GEMM (stream 0, planes 0/1)
        if (wg == 0 && act1) {
            const u32 apl0 = a_base;
            const u32 bb = sbase + S_BF;
            #pragma unroll
            for (int kpg = 0; kpg < 8; ++kpg) KSTEP(apl0, bb, acci, kpg);
        }

        // ---- group-local wait: all 16 CTAs finished phase sph-1
        if (sph > 0) {
            if (tid == 0) {
                unsigned tgt = 16u * (unsigned)sph;
                while (*(volatile unsigned*)ctr < tgt) { }
                __threadfence();
            }
            __syncthreads();
        }

        // ---- stage h1(sph) slot sph&1 and h2(sph-1) slot (sph-1)&1
        {
            const int s1 = sph & 1, s2 = (sph - 1) & 1;
            STAGE(g_h1hi[s1], g_h1lo[s1], 2, 0);
            STAGE(g_h1hi[s1], g_h1lo[s1], 2, 1);
            CPA_COMMIT();
            STAGE(g_h2hi[s2], g_h2lo[s2], 4, 0);
            STAGE(g_h2hi[s2], g_h2lo[s2], 4, 1);
            CPA_COMMIT();
        }
        CPA_WAIT(0);
        __syncthreads();

        // ---- post-wait GEMMs
        if (myact) {
            if (wg == 0) {
                const u32 apl0 = a_base + 2u * A_PL;          // h1 planes
                const u32 bb = sbase + S_BF + 1u * B_STRM;    // stream 1
                #pragma unroll
                for (int kpg = 0; kpg < 8; ++kpg) KSTEP(apl0, bb, acch, kpg);
            } else {
                const u32 apl_i = a_base + 2u * A_PL;         // h1 planes
                const u32 apl_h = a_base + 4u * A_PL;         // h2 planes
                const u32 bb_i = sbase + S_BF + 2u * B_STRM;  // stream 2
                const u32 bb_h = sbase + S_BF + 3u * B_STRM;  // stream 3
                #pragma unroll
                for (int kpg = 0; kpg < 8; ++kpg) {
                    KSTEP(apl_i, bb_i, acci, kpg);
                    KSTEP(apl_h, bb_h, acch, kpg);
                }
            }
        }

        // ---- epilogue: gates in registers, h_old from staged planes
        if (myact) {
            float res[2][2];
            #pragma unroll
            for (int rh = 0; rh < 2; ++rh) {
                u32 hw, lw;
                LDS32(hw, h_base + (u32)(rh * 8) * A_STR);
                LDS32(lw, h_base + (u32)(rh * 8) * A_STR + A_PL);
                __nv_bfloat162 hv = *(__nv_bfloat162*)&hw;
                __nv_bfloat162 lv = *(__nv_bfloat162*)&lw;
                float hold[2] = { __bfloat162float(hv.x) + __bfloat162float(lv.x),
                                  __bfloat162float(hv.y) + __bfloat162float(lv.y) };
                #pragma unroll
                for (int cc = 0; cc < 2; ++cc) {
                    const int k = rh * 2 + cc;
                    float r = sigf(fmaf(s_i, acci[0][k], fmaf(s_h, acch[0][k], bR[cc])));
                    float z = sigf(fmaf(s_i, acci[1][k], fmaf(s_h, acch[1][k], bZ[cc])));
                    float n = tanhf(fmaf(s_i, acci[2][k], bNi[cc])
                                    + r * fmaf(s_h, acch[2][k], bNh[cc]));
                    res[rh][cc] = (1.f - z) * n + z * hold[cc];
                }
            }
            if (wg == 1 && sph == SEQ) {
                *(float2*)(out + (size_t)b_r * 256 + jb) = make_float2(res[0][0], res[0][1]);
                *(float2*)(out + (size_t)(b_r + 8) * 256 + jb) = make_float2(res[1][0], res[1][1]);
            } else {
                __nv_bfloat16* hhi;
                __nv_bfloat16* hlo;
                if (wg == 0) { const int ws = (sph + 1) & 1; hhi = g_h1hi[ws]; hlo = g_h1lo[ws]; }
                else         { const int ws = sph & 1;       hhi = g_h2hi[ws]; hlo = g_h2lo[ws]; }
                #pragma unroll
                for (int rh = 0; rh < 2; ++rh) {
                    const size_t off = (size_t)(b_r + rh * 8) * 256 + jb;
                    __nv_bfloat16 hi0 = __float2bfloat16(res[rh][0]);
                    __nv_bfloat16 hi1 = __float2bfloat16(res[rh][1]);
                    float lo0 = res[rh][0] - __bfloat162float(hi0);
                    float lo1 = res[rh][1] - __bfloat162float(hi1);
                    __nv_bfloat162 hp; hp.x = hi0; hp.y = hi1;
                    *(u32*)(hhi + off) = *(u32*)&hp;
                    *(u32*)(hlo + off) = pkbf(lo0, lo1);
                }
            }
        }

        // ---- arrive
        __syncthreads();
        if (tid == 0) {
            __threadfence();
            atomicAdd(ctr, 1u);
        }
    }
    #undef STAGE
    #undef KSTEP
}

// ---------------- host launch ----------------
extern "C" void kernel_launch(void* const* d_in, const int* in_sizes, int n_in,
                              void* d_out, int out_size) {
    (void)in_sizes; (void)n_in; (void)out_size;
    const float* x     = (const float*)d_in[0];
    const float* h1    = (const float*)d_in[1];
    const float* h2    = (const float*)d_in[2];
    const float* w_ih1 = (const float*)d_in[3];
    const float* w_hh1 = (const float*)d_in[4];
    const float* b_ih1 = (const float*)d_in[5];
    const float* b_hh1 = (const float*)d_in[6];
    const float* w_ih2 = (const float*)d_in[7];
    const float* w_hh2 = (const float*)d_in[8];
    const float* b_ih2 = (const float*)d_in[9];
    const float* b_hh2 = (const float*)d_in[10];
    float* out = (float*)d_out;

    cudaFuncSetAttribute(k_main, cudaFuncAttributeMaxDynamicSharedMemorySize, SMEM_BYTES);

    k_init<<<256, 256>>>(h1, h2);
    k_scales<<<4, 512>>>(w_ih1, w_hh1, w_ih2, w_hh2);
    k_pack<<<512, 256>>>(w_ih1, w_hh1, w_ih2, w_hh2);
    k_convx<<<32768, 256>>>(x);
    k_main<<<128, 256, SMEM_BYTES>>>(b_ih1, b_hh1, b_ih2, b_hh2, out);
}

// round 16
// speedup vs baseline: 1.3397x; 1.0451x over previous
#include <cuda_runtime.h>
#include <cuda_bf16.h>
#include <math.h>
#include <stdint.h>

#define SEQ 512

typedef unsigned int u32;
typedef unsigned long long u64;

// ---------------- device globals (no cudaMalloc allowed) ----------------
// quantized integer-valued weights (bf16-exact), layout gW[k*768 + c], c = gate*256 + j
__device__ float gW1x[256 * 768];
__device__ float gW1h[256 * 768];
__device__ float gW2i[256 * 768];
__device__ float gW2h[256 * 768];

// activations as bf16 hi/lo planes, [b][k] row-major
__device__ __nv_bfloat16 g_xhi[(size_t)SEQ * 65536];
__device__ __nv_bfloat16 g_xlo[(size_t)SEQ * 65536];
// h(m) stored in slot m&1
__device__ __nv_bfloat16 g_h1hi[2][65536];
__device__ __nv_bfloat16 g_h1lo[2][65536];
__device__ __nv_bfloat16 g_h2hi[2][65536];
__device__ __nv_bfloat16 g_h2lo[2][65536];

__device__ float g_scale[4];
// per-bt-group progress counters (one cache line each)
__device__ unsigned g_ctr[8 * 32];

// ---------------- helpers ----------------
__device__ __forceinline__ u32 smem_u32(const void* p) {
    u32 a;
    asm("{ .reg .u64 t; cvta.to.shared.u64 t, %1; cvt.u32.u64 %0, t; }" : "=r"(a) : "l"(p));
    return a;
}

#define LDMATRIX4(r, a) \
    asm volatile("ldmatrix.sync.aligned.m8n8.x4.shared.b16 {%0,%1,%2,%3}, [%4];" \
        : "=r"((r)[0]), "=r"((r)[1]), "=r"((r)[2]), "=r"((r)[3]) : "r"(a))

#define MMA16816(d, a, b0, b1) \
    asm volatile("mma.sync.aligned.m16n8k16.row.col.f32.bf16.bf16.f32 " \
        "{%0,%1,%2,%3}, {%4,%5,%6,%7}, {%8,%9}, {%0,%1,%2,%3};" \
        : "+f"((d)[0]), "+f"((d)[1]), "+f"((d)[2]), "+f"((d)[3]) \
        : "r"((a)[0]), "r"((a)[1]), "r"((a)[2]), "r"((a)[3]), "r"(b0), "r"(b1))

#define LDS128R(r0, r1, r2, r3, a) \
    asm volatile("ld.shared.v4.b32 {%0,%1,%2,%3}, [%4];" \
        : "=r"(r0), "=r"(r1), "=r"(r2), "=r"(r3) : "r"(a))

#define LDS32(r0, a) \
    asm volatile("ld.shared.b32 %0, [%1];" : "=r"(r0) : "r"(a))

#define CPA16(dst, src) \
    asm volatile("cp.async.cg.shared.global [%0], [%1], 16;" :: "r"(dst), "l"(src) : "memory")
#define CPA_COMMIT() asm volatile("cp.async.commit_group;" ::: "memory")
#define CPA_WAIT(N)  asm volatile("cp.async.wait_group %0;" :: "n"(N) : "memory")

__device__ __forceinline__ u32 pkbf(float x, float y) {
    __nv_bfloat162 t = __floats2bfloat162_rn(x, y);
    return *(u32*)&t;
}

__device__ __forceinline__ float sigf(float x) { return 1.f / (1.f + expf(-x)); }

// ---------------- setup kernel 1: counters + h state + scales ----------------
// blocks 0..3: per-tensor max-abs -> scale ; blocks 4..131: init h states
__global__ void k_setup1(const float* __restrict__ h1, const float* __restrict__ h2,
                         const float* __restrict__ w0, const float* __restrict__ w1,
                         const float* __restrict__ w2, const float* __restrict__ w3) {
    if (blockIdx.x < 4) {
        const float* w = (blockIdx.x == 0) ? w0 : (blockIdx.x == 1) ? w1
                       : (blockIdx.x == 2) ? w2 : w3;
        const int n = 768 * 256;
        float m = 0.f;
        for (int i = threadIdx.x; i < n; i += blockDim.x) m = fmaxf(m, fabsf(w[i]));
        __shared__ float sm[512];
        sm[threadIdx.x] = m;
        __syncthreads();
        for (int s = blockDim.x >> 1; s > 0; s >>= 1) {
            if (threadIdx.x < s) sm[threadIdx.x] = fmaxf(sm[threadIdx.x], sm[threadIdx.x + s]);
            __syncthreads();
        }
        if (threadIdx.x == 0) g_scale[blockIdx.x] = sm[0] / 127.0f;
    } else {
        int i = (blockIdx.x - 4) * blockDim.x + threadIdx.x;
        if (blockIdx.x == 4 && threadIdx.x < 256) g_ctr[threadIdx.x] = 0u;
        if (i < 65536) {
            float v1 = h1[i], v2 = h2[i];
            __nv_bfloat16 a = __float2bfloat16(v1);
            g_h1hi[0][i] = a;                                  // h1(0) -> slot 0
            g_h1lo[0][i] = __float2bfloat16(v1 - __bfloat162float(a));
            __nv_bfloat16 b = __float2bfloat16(v2);
            g_h2hi[0][i] = b;                                  // h2(0) -> slot 0
            g_h2lo[0][i] = __float2bfloat16(v2 - __bfloat162float(b));
        }
    }
}

// ---------------- setup kernel 2: weight pack + x conversion ----------------
// blocks 0..511: pack ; blocks 512..33279: x -> bf16 hi/lo planes
__global__ void k_setup2(const float* __restrict__ x,
                         const float* __restrict__ wih1, const float* __restrict__ whh1,
                         const float* __restrict__ wih2, const float* __restrict__ whh2) {
    if (blockIdx.x < 512) {
        const float s0 = g_scale[0], s1 = g_scale[1], s2 = g_scale[2], s3 = g_scale[3];
        const int N = 256 * 768;
        for (int i = blockIdx.x * blockDim.x + threadIdx.x; i < N; i += 512 * 256) {
            int k = i / 768, c = i - k * 768;
            int off = c * 256 + k;
            gW1x[i] = rintf(wih1[off] / s0);
            gW1h[i] = rintf(whh1[off] / s1);
            gW2i[i] = rintf(wih2[off] / s2);
            gW2h[i] = rintf(whh2[off] / s3);
        }
    } else {
        size_t i = ((size_t)(blockIdx.x - 512) * blockDim.x + threadIdx.x) * 4;
        if (i >= (size_t)SEQ * 65536) return;
        float4 v = *(const float4*)(x + i);
        float vv[4] = {v.x, v.y, v.z, v.w};
        __nv_bfloat16 hi[4], lo[4];
        #pragma unroll
        for (int r = 0; r < 4; ++r) {
            hi[r] = __float2bfloat16(vv[r]);
            lo[r] = __float2bfloat16(vv[r] - __bfloat162float(hi[r]));
        }
        *(uint2*)(g_xhi + i) = *(uint2*)hi;
        *(uint2*)(g_xlo + i) = *(uint2*)lo;
    }
}

// ---------------- main persistent kernel ----------------
// 128 CTAs x 256 threads = 8 bt-groups x 16 jt. Per CTA: M=32 rows x N=48 (gate-major),
// warps 0-3 = L1 phase s (h1(s+1)), warps 4-7 = L2 phase s (h2(s)).
// Commit groups per phase: [x][h1][h2]. x latency hides under the counter wait;
// h1/h2 latency hides under L1's x-GEMM (runs between CPA_WAIT(2) and CPA_WAIT(1)).
// A planes (bf16, stride 528): [0]=x-hi [1]=x-lo [2]=h1-hi [3]=h1-lo [4]=h2-hi [5]=h2-lo.
// B frag stream: [stream(4)][tile(6)][kpg(8)][lane(32)][16B], stream = wg*2+src.
#define S_BF   1024
#define S_A    99328
#define A_STR  528
#define A_PL   16896
#define B_STRM 24576
#define SMEM_BYTES 200704

__global__ void __launch_bounds__(256) k_main(
    const float* __restrict__ b_ih1, const float* __restrict__ b_hh1,
    const float* __restrict__ b_ih2, const float* __restrict__ b_hh2,
    float* __restrict__ out)
{
    extern __shared__ char smem[];
    const u32 sbase = smem_u32(smem);
    float* sBias = (float*)smem;

    const int tid = threadIdx.x;
    const int ln = tid & 31, w = tid >> 5;
    const int wg = w >> 2;               // 0 = layer1, 1 = layer2
    const int wm = w & 1;                // 16-row half
    const int wn = (w >> 1) & 1;         // j-half of 8
    const int bid = blockIdx.x;
    const int bt = bid >> 4;
    const int jt = bid & 15;
    const int b0 = bt * 32;
    const int j0 = jt * 16;

    unsigned* ctr = &g_ctr[bt * 32];

    // ---- one-time: B fragment stream (both layers; paired 16B per 2 ksteps)
    {
        const int sB = w & 1;
        const int ksh = (w >> 1) & 1;
        const float* Ws;
        if (wg == 0) Ws = sB ? gW1h : gW1x;
        else         Ws = sB ? gW2h : gW2i;
        const int n = ln >> 2, kp4 = ln & 3;
        for (int ks = ksh * 8; ks < ksh * 8 + 8; ++ks) {
            #pragma unroll
            for (int tt = 0; tt < 6; ++tt) {
                int j = j0 + (tt & 1) * 8 + n;
                int c = (tt >> 1) * 256 + j;
                int k0 = ks * 16 + kp4 * 2;
                u32 f0 = pkbf(Ws[(size_t)k0 * 768 + c], Ws[(size_t)(k0 + 1) * 768 + c]);
                u32 f1 = pkbf(Ws[(size_t)(k0 + 8) * 768 + c], Ws[(size_t)(k0 + 9) * 768 + c]);
                u32 ad = sbase + S_BF
                       + (u32)(((((wg * 2 + sB) * 6 + tt) * 8 + (ks >> 1)) * 32 + ln) * 16)
                       + (u32)((ks & 1) * 8);
                asm volatile("st.shared.v2.b32 [%0], {%1,%2};" :: "r"(ad), "r"(f0), "r"(f1) : "memory");
            }
        }
    }
    if (tid < 32) {
        int lj = tid & 15;
        int j = j0 + lj;
        const float* bi = (tid < 16) ? b_ih1 : b_ih2;
        const float* bh = (tid < 16) ? b_hh1 : b_hh2;
        sBias[tid * 4 + 0] = bi[j] + bh[j];
        sBias[tid * 4 + 1] = bi[j + 256] + bh[j + 256];
        sBias[tid * 4 + 2] = bi[j + 512];
        sBias[tid * 4 + 3] = bh[j + 512];
    }
    const float s_i = (wg == 0) ? g_scale[0] : g_scale[2];
    const float s_h = (wg == 0) ? g_scale[1] : g_scale[3];
    __syncthreads();

    // per-lane constants
    const int jb = j0 + wn * 8 + (ln & 3) * 2;      // global j of col pair
    const int b_r = b0 + wm * 16 + (ln >> 2);       // global batch row
    const int jl = wg * 16 + wn * 8 + (ln & 3) * 2;
    float bR[2], bZ[2], bNi[2], bNh[2];
    #pragma unroll
    for (int cc = 0; cc < 2; ++cc) {
        bR[cc]  = sBias[(jl + cc) * 4 + 0];
        bZ[cc]  = sBias[(jl + cc) * 4 + 1];
        bNi[cc] = sBias[(jl + cc) * 4 + 2];
        bNh[cc] = sBias[(jl + cc) * 4 + 3];
    }
    const u32 a_base = sbase + S_A + (u32)(wm * 16 + (ln & 15)) * A_STR + (u32)((ln >> 4) * 16);
    // h_old planes: L1 -> h1 (planes 2,3); L2 -> h2 (planes 4,5)
    const u32 h_base = sbase + S_A + (u32)(2 + wg * 2) * A_PL
                     + (u32)(wm * 16 + (ln >> 2)) * A_STR + (u32)(jb * 2);
    // staging map: 4 threads per plane-row
    const int st_q   = (tid >> 2) >> 5;        // plane within pair
    const int st_row = (tid >> 2) & 31;
    const int st_seg = (tid & 3) * 64;

    #define STAGE(PHI, PLO, PB, KH) do { \
        const char* _s = (const char*)(st_q ? (const void*)(PLO) : (const void*)(PHI)) \
                       + (size_t)(b0 + st_row) * 512 + (KH) * 256 + st_seg; \
        u32 _d = sbase + S_A + (u32)((PB) + st_q) * A_PL + (u32)st_row * A_STR \
               + (u32)((KH) * 256 + st_seg); \
        CPA16(_d, _s); CPA16(_d + 16, _s + 16); \
        CPA16(_d + 32, _s + 32); CPA16(_d + 48, _s + 48); \
    } while (0)

    // one kpg step (2 ksteps of 16) of one source into ACC[3][4]
    #define KSTEP(APL0, BB, ACC, KPG) do { \
        u32 aE0[4], aE1[4], aO0[4], aO1[4]; \
        LDMATRIX4(aE0, (APL0) + (u32)((KPG) * 64)); \
        LDMATRIX4(aO0, (APL0) + (u32)((KPG) * 64 + 32)); \
        LDMATRIX4(aE1, (APL0) + A_PL + (u32)((KPG) * 64)); \
        LDMATRIX4(aO1, (APL0) + A_PL + (u32)((KPG) * 64 + 32)); \
        _Pragma("unroll") \
        for (int g = 0; g < 3; ++g) { \
            u32 f0, f1, f2, f3; \
            u32 bad = (BB) + (u32)((((g * 2 + wn) * 8 + (KPG)) * 32 + ln) * 16); \
            LDS128R(f0, f1, f2, f3, bad); \
            MMA16816(ACC[g], aE0, f0, f1); \
            MMA16816(ACC[g], aE1, f0, f1); \
            MMA16816(ACC[g], aO0, f2, f3); \
            MMA16816(ACC[g], aO1, f2, f3); \
        } \
    } while (0)

    // GRU epilogue + state store
    #define GATE_STORE() do { \
        float res[2][2]; \
        _Pragma("unroll") \
        for (int rh = 0; rh < 2; ++rh) { \
            u32 hw, lw; \
            LDS32(hw, h_base + (u32)(rh * 8) * A_STR); \
            LDS32(lw, h_base + (u32)(rh * 8) * A_STR + A_PL); \
            __nv_bfloat162 hv = *(__nv_bfloat162*)&hw; \
            __nv_bfloat162 lv = *(__nv_bfloat162*)&lw; \
            float hold[2] = { __bfloat162float(hv.x) + __bfloat162float(lv.x), \
                              __bfloat162float(hv.y) + __bfloat162float(lv.y) }; \
            _Pragma("unroll") \
            for (int cc = 0; cc < 2; ++cc) { \
                const int k = rh * 2 + cc; \
                float r = sigf(fmaf(s_i, acci[0][k], fmaf(s_h, acch[0][k], bR[cc]))); \
                float z = sigf(fmaf(s_i, acci[1][k], fmaf(s_h, acch[1][k], bZ[cc]))); \
                float n = tanhf(fmaf(s_i, acci[2][k], bNi[cc]) \
                                + r * fmaf(s_h, acch[2][k], bNh[cc])); \
                res[rh][cc] = (1.f - z) * n + z * hold[cc]; \
            } \
        } \
        if (wg == 1 && sph == SEQ) { \
            *(float2*)(out + (size_t)b_r * 256 + jb) = make_float2(res[0][0], res[0][1]); \
            *(float2*)(out + (size_t)(b_r + 8) * 256 + jb) = make_float2(res[1][0], res[1][1]); \
        } else { \
            __nv_bfloat16* hhi; \
            __nv_bfloat16* hlo; \
            if (wg == 0) { const int ws = (sph + 1) & 1; hhi = g_h1hi[ws]; hlo = g_h1lo[ws]; } \
            else         { const int ws = sph & 1;       hhi = g_h2hi[ws]; hlo = g_h2lo[ws]; } \
            _Pragma("unroll") \
            for (int rh = 0; rh < 2; ++rh) { \
                const size_t off = (size_t)(b_r + rh * 8) * 256 + jb; \
                __nv_bfloat16 hi0 = __float2bfloat16(res[rh][0]); \
                __nv_bfloat16 hi1 = __float2bfloat16(res[rh][1]); \
                float lo0 = res[rh][0] - __bfloat162float(hi0); \
                float lo1 = res[rh][1] - __bfloat162float(hi1); \
                __nv_bfloat162 hp; hp.x = hi0; hp.y = hi1; \
                *(u32*)(hhi + off) = *(u32*)&hp; \
                *(u32*)(hlo + off) = pkbf(lo0, lo1); \
            } \
        } \
    } while (0)

    for (int sph = 0; sph <= SEQ; ++sph) {
        const bool act1 = (sph < SEQ);
        const bool act2 = (sph >= 1);

        // ---- group [x]: stage x(sph), both k-halves (latency hides under counter wait)
        if (act1) {
            const __nv_bfloat16* xh = g_xhi + (size_t)sph * 65536;
            const __nv_bfloat16* xl = g_xlo + (size_t)sph * 65536;
            STAGE(xh, xl, 0, 0);
            STAGE(xh, xl, 0, 1);
        }
        CPA_COMMIT();

        // ---- group-local wait: all 16 CTAs finished phase sph-1
        if (sph > 0) {
            if (tid == 0) {
                unsigned tgt = 16u * (unsigned)sph;
                while (*(volatile unsigned*)ctr < tgt) { }
                __threadfence();
            }
            __syncthreads();
        }

        // ---- groups [h1], [h2]
        {
            const int s1 = sph & 1, s2 = (sph - 1) & 1;
            STAGE(g_h1hi[s1], g_h1lo[s1], 2, 0);
            STAGE(g_h1hi[s1], g_h1lo[s1], 2, 1);
            CPA_COMMIT();
            STAGE(g_h2hi[s2], g_h2lo[s2], 4, 0);
            STAGE(g_h2hi[s2], g_h2lo[s2], 4, 1);
            CPA_COMMIT();
        }

        float acci[3][4] = {}, acch[3][4] = {};

        // ---- x ready (h still in flight): L1 x-GEMM overlaps h staging latency
        CPA_WAIT(2);
        __syncthreads();
        if (wg == 0 && act1) {
            #pragma unroll
            for (int kpg = 0; kpg < 8; ++kpg)
                KSTEP(a_base, sbase + S_BF, acci, kpg);
        }

        // ---- h1 ready: both layers' h1-GEMMs; L1 epilogue right after (no h2 dep)
        CPA_WAIT(1);
        __syncthreads();
        if (wg == 0) {
            if (act1) {
                #pragma unroll
                for (int kpg = 0; kpg < 8; ++kpg)
                    KSTEP(a_base + 2u * A_PL, sbase + S_BF + 1u * B_STRM, acch, kpg);
                GATE_STORE();
            }
        } else if (act2) {
            #pragma unroll
            for (int kpg = 0; kpg < 8; ++kpg)
                KSTEP(a_base + 2u * A_PL, sbase + S_BF + 2u * B_STRM, acci, kpg);
        }

        // ---- h2 ready: L2 h2-GEMM + epilogue (L1 already done)
        CPA_WAIT(0);
        __syncthreads();
        if (wg == 1 && act2) {
            #pragma unroll
            for (int kpg = 0; kpg < 8; ++kpg)
                KSTEP(a_base + 4u * A_PL, sbase + S_BF + 3u * B_STRM, acch, kpg);
            GATE_STORE();
        }

        // ---- arrive
        __syncthreads();
        if (tid == 0) {
            __threadfence();
            atomicAdd(ctr, 1u);
        }
    }
    #undef STAGE
    #undef KSTEP
    #undef GATE_STORE
}

// ---------------- host launch ----------------
extern "C" void kernel_launch(void* const* d_in, const int* in_sizes, int n_in,
                              void* d_out, int out_size) {
    (void)in_sizes; (void)n_in; (void)out_size;
    const float* x     = (const float*)d_in[0];
    const float* h1    = (const float*)d_in[1];
    const float* h2    = (const float*)d_in[2];
    const float* w_ih1 = (const float*)d_in[3];
    const float* w_hh1 = (const float*)d_in[4];
    const float* b_ih1 = (const float*)d_in[5];
    const float* b_hh1 = (const float*)d_in[6];
    const float* w_ih2 = (const float*)d_in[7];
    const float* w_hh2 = (const float*)d_in[8];
    const float* b_ih2 = (const float*)d_in[9];
    const float* b_hh2 = (const float*)d_in[10];
    float* out = (float*)d_out;

    cudaFuncSetAttribute(k_main, cudaFuncAttributeMaxDynamicSharedMemorySize, SMEM_BYTES);

    k_setup1<<<132, 512>>>(h1, h2, w_ih1, w_hh1, w_ih2, w_hh2);
    k_setup2<<<33280, 256>>>(x, w_ih1, w_hh1, w_ih2, w_hh2);
    k_main<<<128, 256, SMEM_BYTES>>>(b_ih1, b_hh1, b_ih2, b_hh2, out);
}